// round 14
// baseline (speedup 1.0000x reference)
#include <cuda_runtime.h>
#include <cuda_bf16.h>
#include <cfloat>
#include <cstdint>

// ---------------------------------------------------------------------------
// EmbeddingBag mean||max (B=8192 bags over T=409600 tokens, D=128) + Linear
//   feature_seq : int32 [T]
//   offset_seq  : int32 [B]   (sorted bag starts, offs[0]==0)
//   W           : f32   [VOCAB, 128]
//   L           : f32   [128, 256]
//   out         : f32   [B, 128] = concat(mean, max) @ L^T
// ---------------------------------------------------------------------------

#define D 128
#define K2 256
#define MAX_B 8192

__device__ __align__(16) float g_men[MAX_B * K2];   // [B, 256], tf32-rounded
__device__ __align__(16) float g_L32[128 * K2];     // L, tf32-rounded

__device__ __forceinline__ float f2tf32r(float f) {
    uint32_t r;
    asm("cvt.rna.tf32.f32 %0, %1;" : "=r"(r) : "f"(f));
    return __uint_as_float(r);
}

// ============================================================================
// Kernel 1: PERSISTENT block-per-bag. grid = 1184 (8 blocks/SM exactly, one
// wave); each block loops over bags stride-gridDim. Kills 6 of 7 wave
// transitions and averages bag-size imbalance across the whole run.
// 8 warps take contiguous chunks; x8-unrolled gather (MLP=8); smem combine.
// Blocks 0..31 also write tf32-rounded L into g_L32.
// ============================================================================
__global__ void __launch_bounds__(256) bag_reduce_kernel(
    const int* __restrict__ feat,
    const int* __restrict__ offs,
    const float* __restrict__ W,
    const float* __restrict__ L,
    int T, int B)
{
    __shared__ float4 Ss[8][32];
    __shared__ float4 Sm[8][32];

    const int tid  = threadIdx.x;
    const int w    = tid >> 5;
    const int lane = tid & 31;

    if (blockIdx.x < 32) {   // side task: round L into g_L32
        const int base = blockIdx.x * 1024 + tid * 4;
        const float4 v = *reinterpret_cast<const float4*>(&L[base]);
        float4 r;
        r.x = f2tf32r(v.x); r.y = f2tf32r(v.y);
        r.z = f2tf32r(v.z); r.w = f2tf32r(v.w);
        *reinterpret_cast<float4*>(&g_L32[base]) = r;
    }

    const float4* __restrict__ Wv = (const float4*)W;   // row stride = 32 float4

    for (int bag = blockIdx.x; bag < B; bag += gridDim.x) {
        const int start = offs[bag];
        const int end   = (bag == B - 1) ? T : offs[bag + 1];
        const int cnt   = end - start;

        float4 s = make_float4(0.f, 0.f, 0.f, 0.f);
        float4 m = make_float4(-FLT_MAX, -FLT_MAX, -FLT_MAX, -FLT_MAX);

        const int chunk = (cnt + 7) >> 3;
        const int cs = start + w * chunk;
        const int ce = min(cs + chunk, end);

        int t = cs;
        for (; t + 8 <= ce; t += 8) {
            int f[8];
#pragma unroll
            for (int i = 0; i < 8; ++i) f[i] = __ldg(&feat[t + i]);
            float4 v[8];
#pragma unroll
            for (int i = 0; i < 8; ++i) v[i] = __ldg(&Wv[f[i] * 32 + lane]);
#pragma unroll
            for (int i = 0; i < 8; ++i) {
                s.x += v[i].x; s.y += v[i].y; s.z += v[i].z; s.w += v[i].w;
                m.x = fmaxf(m.x, v[i].x); m.y = fmaxf(m.y, v[i].y);
                m.z = fmaxf(m.z, v[i].z); m.w = fmaxf(m.w, v[i].w);
            }
        }
        for (; t + 4 <= ce; t += 4) {
            const int f0 = __ldg(&feat[t + 0]);
            const int f1 = __ldg(&feat[t + 1]);
            const int f2 = __ldg(&feat[t + 2]);
            const int f3 = __ldg(&feat[t + 3]);
            const float4 v0 = __ldg(&Wv[f0 * 32 + lane]);
            const float4 v1 = __ldg(&Wv[f1 * 32 + lane]);
            const float4 v2 = __ldg(&Wv[f2 * 32 + lane]);
            const float4 v3 = __ldg(&Wv[f3 * 32 + lane]);
            s.x += v0.x + v1.x + v2.x + v3.x;
            s.y += v0.y + v1.y + v2.y + v3.y;
            s.z += v0.z + v1.z + v2.z + v3.z;
            s.w += v0.w + v1.w + v2.w + v3.w;
            m.x = fmaxf(m.x, fmaxf(fmaxf(v0.x, v1.x), fmaxf(v2.x, v3.x)));
            m.y = fmaxf(m.y, fmaxf(fmaxf(v0.y, v1.y), fmaxf(v2.y, v3.y)));
            m.z = fmaxf(m.z, fmaxf(fmaxf(v0.z, v1.z), fmaxf(v2.z, v3.z)));
            m.w = fmaxf(m.w, fmaxf(fmaxf(v0.w, v1.w), fmaxf(v2.w, v3.w)));
        }
        const int rem = ce - t;
        if (rem > 0) {
            const int i1 = (rem > 1) ? t + 1 : t;
            const int i2 = (rem > 2) ? t + 2 : t;
            const int f0 = __ldg(&feat[t]);
            const int f1 = __ldg(&feat[i1]);
            const int f2 = __ldg(&feat[i2]);
            const float4 v0 = __ldg(&Wv[f0 * 32 + lane]);
            const float4 v1 = __ldg(&Wv[f1 * 32 + lane]);
            const float4 v2 = __ldg(&Wv[f2 * 32 + lane]);
            const float k1 = (rem > 1) ? 1.f : 0.f;
            const float k2 = (rem > 2) ? 1.f : 0.f;
            s.x += v0.x + k1 * v1.x + k2 * v2.x;
            s.y += v0.y + k1 * v1.y + k2 * v2.y;
            s.z += v0.z + k1 * v1.z + k2 * v2.z;
            s.w += v0.w + k1 * v1.w + k2 * v2.w;
            m.x = fmaxf(m.x, v0.x); m.y = fmaxf(m.y, v0.y);
            m.z = fmaxf(m.z, v0.z); m.w = fmaxf(m.w, v0.w);
            if (rem > 1) {
                m.x = fmaxf(m.x, v1.x); m.y = fmaxf(m.y, v1.y);
                m.z = fmaxf(m.z, v1.z); m.w = fmaxf(m.w, v1.w);
            }
            if (rem > 2) {
                m.x = fmaxf(m.x, v2.x); m.y = fmaxf(m.y, v2.y);
                m.z = fmaxf(m.z, v2.z); m.w = fmaxf(m.w, v2.w);
            }
        }

        Ss[w][lane] = s;
        Sm[w][lane] = m;
        __syncthreads();

        if (tid < 32) {
            float4 rs = Ss[0][lane];
            float4 rm = Sm[0][lane];
#pragma unroll
            for (int i = 1; i < 8; ++i) {
                const float4 a = Ss[i][lane];
                const float4 b = Sm[i][lane];
                rs.x += a.x; rs.y += a.y; rs.z += a.z; rs.w += a.w;
                rm.x = fmaxf(rm.x, b.x); rm.y = fmaxf(rm.y, b.y);
                rm.z = fmaxf(rm.z, b.z); rm.w = fmaxf(rm.w, b.w);
            }
            const float inv = 1.0f / fmaxf((float)cnt, 1.0f);
            float4 mean;
            mean.x = f2tf32r(rs.x * inv); mean.y = f2tf32r(rs.y * inv);
            mean.z = f2tf32r(rs.z * inv); mean.w = f2tf32r(rs.w * inv);
            if (cnt == 0) rm = make_float4(0.f, 0.f, 0.f, 0.f);
            float4 mx;
            mx.x = f2tf32r(rm.x); mx.y = f2tf32r(rm.y);
            mx.z = f2tf32r(rm.z); mx.w = f2tf32r(rm.w);

            float4* mp = (float4*)g_men;             // row stride = 64 float4
            mp[bag * 64 + lane]      = mean;         // cols [0,128)
            mp[bag * 64 + 32 + lane] = mx;           // cols [128,256)
        }
        __syncthreads();   // protect Ss/Sm before next bag iteration
    }
}

// ============================================================================
// Kernel 2: C = men @ L^T, mma.sync m16n8k8 tf32, pre-rounded operands.
// BM=64, BN=128 (FULL width -> g_men read exactly once), grid 128 = 1 wave.
// 512 threads = 16 warps as 4x4 (warp tile 16x32). 3-stage cp.async ring.
// ============================================================================
#define BM 64
#define BN 128
#define BK 32
#define LDA (BK + 4)                    // 36 words
#define NIT (K2 / BK)                   // 8
#define STAGES 3
#define STAGE_WORDS ((BM + BN) * LDA)   // 6912 words = 27648 B
#define GEMM_SMEM_BYTES (STAGES * STAGE_WORDS * 4)   // 82944

__device__ __forceinline__ void mma_tf32(float c[4],
                                         uint32_t a0, uint32_t a1, uint32_t a2, uint32_t a3,
                                         uint32_t b0, uint32_t b1) {
    asm volatile(
        "mma.sync.aligned.m16n8k8.row.col.f32.tf32.tf32.f32 "
        "{%0,%1,%2,%3}, {%4,%5,%6,%7}, {%8,%9}, {%0,%1,%2,%3};"
        : "+f"(c[0]), "+f"(c[1]), "+f"(c[2]), "+f"(c[3])
        : "r"(a0), "r"(a1), "r"(a2), "r"(a3), "r"(b0), "r"(b1));
}

__device__ __forceinline__ uint32_t smem_addr_u32(const void* p) {
    uint32_t a;
    asm("{ .reg .u64 t; cvta.to.shared.u64 t, %1; cvt.u32.u64 %0, t; }"
        : "=r"(a) : "l"(p));
    return a;
}
__device__ __forceinline__ void cp_async16(void* smem_dst, const void* gmem_src) {
    asm volatile("cp.async.ca.shared.global [%0], [%1], 16;"
                 :: "r"(smem_addr_u32(smem_dst)), "l"(gmem_src));
}
#define CP_COMMIT() asm volatile("cp.async.commit_group;" ::: "memory")
#define CP_WAIT2()  asm volatile("cp.async.wait_group 2;" ::: "memory")

__global__ void __launch_bounds__(512) men_gemm_kernel(
    float* __restrict__ out,
    int B)
{
    extern __shared__ uint32_t sh[];
    const int tid  = threadIdx.x;
    const int wid  = tid >> 5;
    const int lane = tid & 31;
    const int wr   = wid >> 2;          // warp row 0..3 (16 rows each)
    const int wc   = wid & 3;           // warp col 0..3 (32 cols each)
    const int gp   = lane >> 2;
    const int tg   = lane & 3;
    const int brow0 = blockIdx.x * BM;

    // stage loader: A 64x8 f4 = 512 slots (1/thread), B 128x8 = 1024 (2/thread)
    auto load_stage = [&](int k0, int st) {
        uint32_t* As = sh + st * STAGE_WORDS;
        uint32_t* Bs = As + BM * LDA;
        {
            const int r  = tid >> 3;               // 0..63
            const int kq = (tid & 7) * 4;
            cp_async16(&As[r * LDA + kq], &g_men[(brow0 + r) * K2 + k0 + kq]);
        }
#pragma unroll
        for (int q = 0; q < 2; ++q) {
            const int slot = tid * 2 + q;          // 0..1023
            const int n  = slot >> 3;              // 0..127
            const int kq = (slot & 7) * 4;
            cp_async16(&Bs[n * LDA + kq], &g_L32[n * K2 + k0 + kq]);
        }
        CP_COMMIT();
    };

    float acc[4][4];
#pragma unroll
    for (int j = 0; j < 4; ++j)
#pragma unroll
        for (int v = 0; v < 4; ++v) acc[j][v] = 0.0f;

    // prologue: 2 stages in flight
    load_stage(0 * BK, 0);
    load_stage(1 * BK, 1);

#pragma unroll
    for (int it = 0; it < NIT; ++it) {
        const int st = it % STAGES;
        if (it + 2 < NIT) load_stage((it + 2) * BK, (it + 2) % STAGES);
        else              CP_COMMIT();          // empty group keeps wait uniform
        CP_WAIT2();                             // stage `it` complete
        __syncthreads();

        const uint32_t* As = sh + st * STAGE_WORDS;
        const uint32_t* Bs = As + BM * LDA;
#pragma unroll
        for (int ks = 0; ks < BK; ks += 8) {
            const int r = wr * 16 + gp;
            const uint32_t a0 = As[r * LDA + ks + tg];
            const uint32_t a1 = As[(r + 8) * LDA + ks + tg];
            const uint32_t a2 = As[r * LDA + ks + tg + 4];
            const uint32_t a3 = As[(r + 8) * LDA + ks + tg + 4];
#pragma unroll
            for (int nt = 0; nt < 4; ++nt) {
                const int n = wc * 32 + nt * 8 + gp;
                const uint32_t b0 = Bs[n * LDA + ks + tg];
                const uint32_t b1 = Bs[n * LDA + ks + tg + 4];
                mma_tf32(acc[nt], a0, a1, a2, a3, b0, b1);
            }
        }
        __syncthreads();
    }

    // epilogue
#pragma unroll
    for (int nt = 0; nt < 4; ++nt) {
        const int row = brow0 + wr * 16 + gp;
        const int col = wc * 32 + nt * 8 + tg * 2;
        float2* o0 = reinterpret_cast<float2*>(&out[row * 128 + col]);
        float2* o1 = reinterpret_cast<float2*>(&out[(row + 8) * 128 + col]);
        *o0 = make_float2(acc[nt][0], acc[nt][1]);
        *o1 = make_float2(acc[nt][2], acc[nt][3]);
    }
}

// no-op padding kernels: shift ncu's "-s 5 -c 1" capture onto K1
// (pattern per call: K1,K2,nop,nop,nop -> launch #6 = K1)
__global__ void nop_kernel() {}

// ---------------------------------------------------------------------------
extern "C" void kernel_launch(void* const* d_in, const int* in_sizes, int n_in,
                              void* d_out, int out_size)
{
    const int*   feat = (const int*)d_in[0];
    const int*   offs = (const int*)d_in[1];
    const float* W    = (const float*)d_in[2];
    const float* L    = (const float*)d_in[3];
    float*       out  = (float*)d_out;

    const int T = in_sizes[0];
    const int B = in_sizes[1];

    cudaFuncSetAttribute(men_gemm_kernel,
                         cudaFuncAttributeMaxDynamicSharedMemorySize,
                         GEMM_SMEM_BYTES);

    bag_reduce_kernel<<<1184, 256>>>(feat, offs, W, L, T, B);
    men_gemm_kernel<<<B / BM, 512, GEMM_SMEM_BYTES>>>(out, B);

    nop_kernel<<<1, 1>>>();
    nop_kernel<<<1, 1>>>();
    nop_kernel<<<1, 1>>>();
}

// round 15
// speedup vs baseline: 1.0962x; 1.0962x over previous
#include <cuda_runtime.h>
#include <cuda_bf16.h>
#include <cfloat>
#include <cstdint>

// ---------------------------------------------------------------------------
// EmbeddingBag mean||max (B=8192 bags over T=409600 tokens, D=128) + Linear
//   feature_seq : int32 [T]
//   offset_seq  : int32 [B]   (sorted bag starts, offs[0]==0)
//   W           : f32   [VOCAB, 128]
//   L           : f32   [128, 256]
//   out         : f32   [B, 128] = concat(mean, max) @ L^T
// ---------------------------------------------------------------------------

#define D 128
#define K2 256
#define MAX_B 8192

__device__ __align__(16) float g_men[MAX_B * K2];   // [B, 256], tf32-rounded
__device__ __align__(16) float g_L32[128 * K2];     // L, tf32-rounded

__device__ __forceinline__ float f2tf32r(float f) {
    uint32_t r;
    asm("cvt.rna.tf32.f32 %0, %1;" : "=r"(r) : "f"(f));
    return __uint_as_float(r);
}

// ============================================================================
// Kernel 1: PERSISTENT block-per-bag. grid = 1184 (8 blocks/SM, one wave);
// each block loops over bags stride-gridDim: no wave transitions, bag-size
// imbalance averaged over ~7 bags/block.
// 8 warps take contiguous chunks; x8-unrolled gather (MLP=8); smem combine.
// Blocks 0..31 also write tf32-rounded L into g_L32.
// ============================================================================
__global__ void __launch_bounds__(256) bag_reduce_kernel(
    const int* __restrict__ feat,
    const int* __restrict__ offs,
    const float* __restrict__ W,
    const float* __restrict__ L,
    int T, int B)
{
    __shared__ float4 Ss[8][32];
    __shared__ float4 Sm[8][32];

    const int tid  = threadIdx.x;
    const int w    = tid >> 5;
    const int lane = tid & 31;

    if (blockIdx.x < 32) {   // side task: round L into g_L32
        const int base = blockIdx.x * 1024 + tid * 4;
        const float4 v = *reinterpret_cast<const float4*>(&L[base]);
        float4 r;
        r.x = f2tf32r(v.x); r.y = f2tf32r(v.y);
        r.z = f2tf32r(v.z); r.w = f2tf32r(v.w);
        *reinterpret_cast<float4*>(&g_L32[base]) = r;
    }

    const float4* __restrict__ Wv = (const float4*)W;   // row stride = 32 float4

    for (int bag = blockIdx.x; bag < B; bag += gridDim.x) {
        const int start = offs[bag];
        const int end   = (bag == B - 1) ? T : offs[bag + 1];
        const int cnt   = end - start;

        float4 s = make_float4(0.f, 0.f, 0.f, 0.f);
        float4 m = make_float4(-FLT_MAX, -FLT_MAX, -FLT_MAX, -FLT_MAX);

        const int chunk = (cnt + 7) >> 3;
        const int cs = start + w * chunk;
        const int ce = min(cs + chunk, end);

        int t = cs;
        for (; t + 8 <= ce; t += 8) {
            int f[8];
#pragma unroll
            for (int i = 0; i < 8; ++i) f[i] = __ldg(&feat[t + i]);
            float4 v[8];
#pragma unroll
            for (int i = 0; i < 8; ++i) v[i] = __ldg(&Wv[f[i] * 32 + lane]);
#pragma unroll
            for (int i = 0; i < 8; ++i) {
                s.x += v[i].x; s.y += v[i].y; s.z += v[i].z; s.w += v[i].w;
                m.x = fmaxf(m.x, v[i].x); m.y = fmaxf(m.y, v[i].y);
                m.z = fmaxf(m.z, v[i].z); m.w = fmaxf(m.w, v[i].w);
            }
        }
        for (; t + 4 <= ce; t += 4) {
            const int f0 = __ldg(&feat[t + 0]);
            const int f1 = __ldg(&feat[t + 1]);
            const int f2 = __ldg(&feat[t + 2]);
            const int f3 = __ldg(&feat[t + 3]);
            const float4 v0 = __ldg(&Wv[f0 * 32 + lane]);
            const float4 v1 = __ldg(&Wv[f1 * 32 + lane]);
            const float4 v2 = __ldg(&Wv[f2 * 32 + lane]);
            const float4 v3 = __ldg(&Wv[f3 * 32 + lane]);
            s.x += v0.x + v1.x + v2.x + v3.x;
            s.y += v0.y + v1.y + v2.y + v3.y;
            s.z += v0.z + v1.z + v2.z + v3.z;
            s.w += v0.w + v1.w + v2.w + v3.w;
            m.x = fmaxf(m.x, fmaxf(fmaxf(v0.x, v1.x), fmaxf(v2.x, v3.x)));
            m.y = fmaxf(m.y, fmaxf(fmaxf(v0.y, v1.y), fmaxf(v2.y, v3.y)));
            m.z = fmaxf(m.z, fmaxf(fmaxf(v0.z, v1.z), fmaxf(v2.z, v3.z)));
            m.w = fmaxf(m.w, fmaxf(fmaxf(v0.w, v1.w), fmaxf(v2.w, v3.w)));
        }
        const int rem = ce - t;
        if (rem > 0) {
            const int i1 = (rem > 1) ? t + 1 : t;
            const int i2 = (rem > 2) ? t + 2 : t;
            const int f0 = __ldg(&feat[t]);
            const int f1 = __ldg(&feat[i1]);
            const int f2 = __ldg(&feat[i2]);
            const float4 v0 = __ldg(&Wv[f0 * 32 + lane]);
            const float4 v1 = __ldg(&Wv[f1 * 32 + lane]);
            const float4 v2 = __ldg(&Wv[f2 * 32 + lane]);
            const float k1 = (rem > 1) ? 1.f : 0.f;
            const float k2 = (rem > 2) ? 1.f : 0.f;
            s.x += v0.x + k1 * v1.x + k2 * v2.x;
            s.y += v0.y + k1 * v1.y + k2 * v2.y;
            s.z += v0.z + k1 * v1.z + k2 * v2.z;
            s.w += v0.w + k1 * v1.w + k2 * v2.w;
            m.x = fmaxf(m.x, v0.x); m.y = fmaxf(m.y, v0.y);
            m.z = fmaxf(m.z, v0.z); m.w = fmaxf(m.w, v0.w);
            if (rem > 1) {
                m.x = fmaxf(m.x, v1.x); m.y = fmaxf(m.y, v1.y);
                m.z = fmaxf(m.z, v1.z); m.w = fmaxf(m.w, v1.w);
            }
            if (rem > 2) {
                m.x = fmaxf(m.x, v2.x); m.y = fmaxf(m.y, v2.y);
                m.z = fmaxf(m.z, v2.z); m.w = fmaxf(m.w, v2.w);
            }
        }

        Ss[w][lane] = s;
        Sm[w][lane] = m;
        __syncthreads();

        if (tid < 32) {
            float4 rs = Ss[0][lane];
            float4 rm = Sm[0][lane];
#pragma unroll
            for (int i = 1; i < 8; ++i) {
                const float4 a = Ss[i][lane];
                const float4 b = Sm[i][lane];
                rs.x += a.x; rs.y += a.y; rs.z += a.z; rs.w += a.w;
                rm.x = fmaxf(rm.x, b.x); rm.y = fmaxf(rm.y, b.y);
                rm.z = fmaxf(rm.z, b.z); rm.w = fmaxf(rm.w, b.w);
            }
            const float inv = 1.0f / fmaxf((float)cnt, 1.0f);
            float4 mean;
            mean.x = f2tf32r(rs.x * inv); mean.y = f2tf32r(rs.y * inv);
            mean.z = f2tf32r(rs.z * inv); mean.w = f2tf32r(rs.w * inv);
            if (cnt == 0) rm = make_float4(0.f, 0.f, 0.f, 0.f);
            float4 mx;
            mx.x = f2tf32r(rm.x); mx.y = f2tf32r(rm.y);
            mx.z = f2tf32r(rm.z); mx.w = f2tf32r(rm.w);

            float4* mp = (float4*)g_men;             // row stride = 64 float4
            mp[bag * 64 + lane]      = mean;         // cols [0,128)
            mp[bag * 64 + 32 + lane] = mx;           // cols [128,256)
        }
        __syncthreads();   // protect Ss/Sm before next bag iteration
    }
}

// ============================================================================
// Kernel 2: C = men @ L^T, mma.sync m16n8k8 tf32, pre-rounded operands.
// BM=64, BN=128 (full width -> g_men read exactly once), grid 128 = 1 wave.
// 512 threads = 16 warps as 4x4 (warp tile 16x32). 3-stage cp.async ring.
// ============================================================================
#define BM 64
#define BN 128
#define BK 32
#define LDA (BK + 4)                    // 36 words
#define NIT (K2 / BK)                   // 8
#define STAGES 3
#define STAGE_WORDS ((BM + BN) * LDA)   // 6912 words = 27648 B
#define GEMM_SMEM_BYTES (STAGES * STAGE_WORDS * 4)   // 82944

__device__ __forceinline__ void mma_tf32(float c[4],
                                         uint32_t a0, uint32_t a1, uint32_t a2, uint32_t a3,
                                         uint32_t b0, uint32_t b1) {
    asm volatile(
        "mma.sync.aligned.m16n8k8.row.col.f32.tf32.tf32.f32 "
        "{%0,%1,%2,%3}, {%4,%5,%6,%7}, {%8,%9}, {%0,%1,%2,%3};"
        : "+f"(c[0]), "+f"(c[1]), "+f"(c[2]), "+f"(c[3])
        : "r"(a0), "r"(a1), "r"(a2), "r"(a3), "r"(b0), "r"(b1));
}

__device__ __forceinline__ uint32_t smem_addr_u32(const void* p) {
    uint32_t a;
    asm("{ .reg .u64 t; cvta.to.shared.u64 t, %1; cvt.u32.u64 %0, t; }"
        : "=r"(a) : "l"(p));
    return a;
}
__device__ __forceinline__ void cp_async16(void* smem_dst, const void* gmem_src) {
    asm volatile("cp.async.ca.shared.global [%0], [%1], 16;"
                 :: "r"(smem_addr_u32(smem_dst)), "l"(gmem_src));
}
#define CP_COMMIT() asm volatile("cp.async.commit_group;" ::: "memory")
#define CP_WAIT2()  asm volatile("cp.async.wait_group 2;" ::: "memory")

__global__ void __launch_bounds__(512) men_gemm_kernel(
    float* __restrict__ out,
    int B)
{
    extern __shared__ uint32_t sh[];
    const int tid  = threadIdx.x;
    const int wid  = tid >> 5;
    const int lane = tid & 31;
    const int wr   = wid >> 2;          // warp row 0..3 (16 rows each)
    const int wc   = wid & 3;           // warp col 0..3 (32 cols each)
    const int gp   = lane >> 2;
    const int tg   = lane & 3;
    const int brow0 = blockIdx.x * BM;

    // stage loader: A 64x8 f4 = 512 slots (1/thread), B 128x8 = 1024 (2/thread)
    auto load_stage = [&](int k0, int st) {
        uint32_t* As = sh + st * STAGE_WORDS;
        uint32_t* Bs = As + BM * LDA;
        {
            const int r  = tid >> 3;               // 0..63
            const int kq = (tid & 7) * 4;
            cp_async16(&As[r * LDA + kq], &g_men[(brow0 + r) * K2 + k0 + kq]);
        }
#pragma unroll
        for (int q = 0; q < 2; ++q) {
            const int slot = tid * 2 + q;          // 0..1023
            const int n  = slot >> 3;              // 0..127
            const int kq = (slot & 7) * 4;
            cp_async16(&Bs[n * LDA + kq], &g_L32[n * K2 + k0 + kq]);
        }
        CP_COMMIT();
    };

    float acc[4][4];
#pragma unroll
    for (int j = 0; j < 4; ++j)
#pragma unroll
        for (int v = 0; v < 4; ++v) acc[j][v] = 0.0f;

    // prologue: 2 stages in flight
    load_stage(0 * BK, 0);
    load_stage(1 * BK, 1);

#pragma unroll
    for (int it = 0; it < NIT; ++it) {
        const int st = it % STAGES;
        if (it + 2 < NIT) load_stage((it + 2) * BK, (it + 2) % STAGES);
        else              CP_COMMIT();          // empty group keeps wait uniform
        CP_WAIT2();                             // stage `it` complete
        __syncthreads();

        const uint32_t* As = sh + st * STAGE_WORDS;
        const uint32_t* Bs = As + BM * LDA;
#pragma unroll
        for (int ks = 0; ks < BK; ks += 8) {
            const int r = wr * 16 + gp;
            const uint32_t a0 = As[r * LDA + ks + tg];
            const uint32_t a1 = As[(r + 8) * LDA + ks + tg];
            const uint32_t a2 = As[r * LDA + ks + tg + 4];
            const uint32_t a3 = As[(r + 8) * LDA + ks + tg + 4];
#pragma unroll
            for (int nt = 0; nt < 4; ++nt) {
                const int n = wc * 32 + nt * 8 + gp;
                const uint32_t b0 = Bs[n * LDA + ks + tg];
                const uint32_t b1 = Bs[n * LDA + ks + tg + 4];
                mma_tf32(acc[nt], a0, a1, a2, a3, b0, b1);
            }
        }
        __syncthreads();
    }

    // epilogue
#pragma unroll
    for (int nt = 0; nt < 4; ++nt) {
        const int row = brow0 + wr * 16 + gp;
        const int col = wc * 32 + nt * 8 + tg * 2;
        float2* o0 = reinterpret_cast<float2*>(&out[row * 128 + col]);
        float2* o1 = reinterpret_cast<float2*>(&out[(row + 8) * 128 + col]);
        *o0 = make_float2(acc[nt][0], acc[nt][1]);
        *o1 = make_float2(acc[nt][2], acc[nt][3]);
    }
}

// ---------------------------------------------------------------------------
extern "C" void kernel_launch(void* const* d_in, const int* in_sizes, int n_in,
                              void* d_out, int out_size)
{
    const int*   feat = (const int*)d_in[0];
    const int*   offs = (const int*)d_in[1];
    const float* W    = (const float*)d_in[2];
    const float* L    = (const float*)d_in[3];
    float*       out  = (float*)d_out;

    const int T = in_sizes[0];
    const int B = in_sizes[1];

    cudaFuncSetAttribute(men_gemm_kernel,
                         cudaFuncAttributeMaxDynamicSharedMemorySize,
                         GEMM_SMEM_BYTES);

    bag_reduce_kernel<<<1184, 256>>>(feat, offs, W, L, T, B);
    men_gemm_kernel<<<B / BM, 512, GEMM_SMEM_BYTES>>>(out, B);
}

// round 16
// speedup vs baseline: 1.2207x; 1.1135x over previous
#include <cuda_runtime.h>
#include <cuda_bf16.h>
#include <cfloat>
#include <cstdint>

// ---------------------------------------------------------------------------
// EmbeddingBag mean||max (B=8192 bags over T=409600 tokens, D=128) + Linear
//   feature_seq : int32 [T]
//   offset_seq  : int32 [B]   (sorted bag starts, offs[0]==0)
//   W           : f32   [VOCAB, 128]
//   L           : f32   [128, 256]
//   out         : f32   [B, 128] = concat(mean, max) @ L^T
// ---------------------------------------------------------------------------

#define D 128
#define K2 256
#define MAX_B 8192

__device__ __align__(16) float g_men[MAX_B * K2];   // [B, 256], tf32-rounded
__device__ __align__(16) float g_L32[128 * K2];     // L, tf32-rounded

__device__ __forceinline__ float f2tf32r(float f) {
    uint32_t r;
    asm("cvt.rna.tf32.f32 %0, %1;" : "=r"(r) : "f"(f));
    return __uint_as_float(r);
}

// ============================================================================
// Kernel 1 (R12-best): block-per-bag, 8 warps take contiguous chunks,
// x8-unrolled gather (MLP=8) + x4 + predicated remainder; smem combine.
// Blocks 0..31 also write tf32-rounded L into g_L32.
// Measured at the ~25us LTS gather floor across all scheduling variants.
// ============================================================================
__global__ void __launch_bounds__(256) bag_reduce_kernel(
    const int* __restrict__ feat,
    const int* __restrict__ offs,
    const float* __restrict__ W,
    const float* __restrict__ L,
    int T, int B)
{
    const int bag  = blockIdx.x;
    const int w    = threadIdx.x >> 5;
    const int lane = threadIdx.x & 31;

    if (bag < 32) {   // side task: round L into g_L32
        const int base = bag * 1024 + threadIdx.x * 4;
        const float4 v = *reinterpret_cast<const float4*>(&L[base]);
        float4 r;
        r.x = f2tf32r(v.x); r.y = f2tf32r(v.y);
        r.z = f2tf32r(v.z); r.w = f2tf32r(v.w);
        *reinterpret_cast<float4*>(&g_L32[base]) = r;
    }

    const int start = offs[bag];
    const int end   = (bag == B - 1) ? T : offs[bag + 1];
    const int cnt   = end - start;

    const float4* __restrict__ Wv = (const float4*)W;   // row stride = 32 float4

    float4 s = make_float4(0.f, 0.f, 0.f, 0.f);
    float4 m = make_float4(-FLT_MAX, -FLT_MAX, -FLT_MAX, -FLT_MAX);

    const int chunk = (cnt + 7) >> 3;
    const int cs = start + w * chunk;
    const int ce = min(cs + chunk, end);

    int t = cs;
    for (; t + 8 <= ce; t += 8) {
        int f[8];
#pragma unroll
        for (int i = 0; i < 8; ++i) f[i] = __ldg(&feat[t + i]);
        float4 v[8];
#pragma unroll
        for (int i = 0; i < 8; ++i) v[i] = __ldg(&Wv[f[i] * 32 + lane]);
#pragma unroll
        for (int i = 0; i < 8; ++i) {
            s.x += v[i].x; s.y += v[i].y; s.z += v[i].z; s.w += v[i].w;
            m.x = fmaxf(m.x, v[i].x); m.y = fmaxf(m.y, v[i].y);
            m.z = fmaxf(m.z, v[i].z); m.w = fmaxf(m.w, v[i].w);
        }
    }
    for (; t + 4 <= ce; t += 4) {
        const int f0 = __ldg(&feat[t + 0]);
        const int f1 = __ldg(&feat[t + 1]);
        const int f2 = __ldg(&feat[t + 2]);
        const int f3 = __ldg(&feat[t + 3]);
        const float4 v0 = __ldg(&Wv[f0 * 32 + lane]);
        const float4 v1 = __ldg(&Wv[f1 * 32 + lane]);
        const float4 v2 = __ldg(&Wv[f2 * 32 + lane]);
        const float4 v3 = __ldg(&Wv[f3 * 32 + lane]);
        s.x += v0.x + v1.x + v2.x + v3.x;
        s.y += v0.y + v1.y + v2.y + v3.y;
        s.z += v0.z + v1.z + v2.z + v3.z;
        s.w += v0.w + v1.w + v2.w + v3.w;
        m.x = fmaxf(m.x, fmaxf(fmaxf(v0.x, v1.x), fmaxf(v2.x, v3.x)));
        m.y = fmaxf(m.y, fmaxf(fmaxf(v0.y, v1.y), fmaxf(v2.y, v3.y)));
        m.z = fmaxf(m.z, fmaxf(fmaxf(v0.z, v1.z), fmaxf(v2.z, v3.z)));
        m.w = fmaxf(m.w, fmaxf(fmaxf(v0.w, v1.w), fmaxf(v2.w, v3.w)));
    }
    const int rem = ce - t;
    if (rem > 0) {
        const int i1 = (rem > 1) ? t + 1 : t;
        const int i2 = (rem > 2) ? t + 2 : t;
        const int f0 = __ldg(&feat[t]);
        const int f1 = __ldg(&feat[i1]);
        const int f2 = __ldg(&feat[i2]);
        const float4 v0 = __ldg(&Wv[f0 * 32 + lane]);
        const float4 v1 = __ldg(&Wv[f1 * 32 + lane]);
        const float4 v2 = __ldg(&Wv[f2 * 32 + lane]);
        const float k1 = (rem > 1) ? 1.f : 0.f;
        const float k2 = (rem > 2) ? 1.f : 0.f;
        s.x += v0.x + k1 * v1.x + k2 * v2.x;
        s.y += v0.y + k1 * v1.y + k2 * v2.y;
        s.z += v0.z + k1 * v1.z + k2 * v2.z;
        s.w += v0.w + k1 * v1.w + k2 * v2.w;
        m.x = fmaxf(m.x, v0.x); m.y = fmaxf(m.y, v0.y);
        m.z = fmaxf(m.z, v0.z); m.w = fmaxf(m.w, v0.w);
        if (rem > 1) {
            m.x = fmaxf(m.x, v1.x); m.y = fmaxf(m.y, v1.y);
            m.z = fmaxf(m.z, v1.z); m.w = fmaxf(m.w, v1.w);
        }
        if (rem > 2) {
            m.x = fmaxf(m.x, v2.x); m.y = fmaxf(m.y, v2.y);
            m.z = fmaxf(m.z, v2.z); m.w = fmaxf(m.w, v2.w);
        }
    }

    __shared__ float4 Ss[8][32];
    __shared__ float4 Sm[8][32];
    Ss[w][lane] = s;
    Sm[w][lane] = m;
    __syncthreads();

    if (threadIdx.x < 32) {
        float4 rs = Ss[0][lane];
        float4 rm = Sm[0][lane];
#pragma unroll
        for (int i = 1; i < 8; ++i) {
            const float4 a = Ss[i][lane];
            const float4 b = Sm[i][lane];
            rs.x += a.x; rs.y += a.y; rs.z += a.z; rs.w += a.w;
            rm.x = fmaxf(rm.x, b.x); rm.y = fmaxf(rm.y, b.y);
            rm.z = fmaxf(rm.z, b.z); rm.w = fmaxf(rm.w, b.w);
        }
        const float inv = 1.0f / fmaxf((float)cnt, 1.0f);
        float4 mean;
        mean.x = f2tf32r(rs.x * inv); mean.y = f2tf32r(rs.y * inv);
        mean.z = f2tf32r(rs.z * inv); mean.w = f2tf32r(rs.w * inv);
        if (cnt == 0) rm = make_float4(0.f, 0.f, 0.f, 0.f);
        float4 mx;
        mx.x = f2tf32r(rm.x); mx.y = f2tf32r(rm.y);
        mx.z = f2tf32r(rm.z); mx.w = f2tf32r(rm.w);

        float4* mp = (float4*)g_men;                 // row stride = 64 float4
        mp[bag * 64 + lane]      = mean;             // cols [0,128)
        mp[bag * 64 + 32 + lane] = mx;               // cols [128,256)
    }
}

// ============================================================================
// Kernel 2 (R15-best): C = men @ L^T, mma.sync m16n8k8 tf32, pre-rounded.
// BM=64, BN=128 (full width -> g_men read exactly once), grid 128 = 1 wave.
// 512 threads = 16 warps as 4x4 (warp tile 16x32). 3-stage cp.async ring.
// ============================================================================
#define BM 64
#define BN 128
#define BK 32
#define LDA (BK + 4)                    // 36 words
#define NIT (K2 / BK)                   // 8
#define STAGES 3
#define STAGE_WORDS ((BM + BN) * LDA)   // 6912 words = 27648 B
#define GEMM_SMEM_BYTES (STAGES * STAGE_WORDS * 4)   // 82944

__device__ __forceinline__ void mma_tf32(float c[4],
                                         uint32_t a0, uint32_t a1, uint32_t a2, uint32_t a3,
                                         uint32_t b0, uint32_t b1) {
    asm volatile(
        "mma.sync.aligned.m16n8k8.row.col.f32.tf32.tf32.f32 "
        "{%0,%1,%2,%3}, {%4,%5,%6,%7}, {%8,%9}, {%0,%1,%2,%3};"
        : "+f"(c[0]), "+f"(c[1]), "+f"(c[2]), "+f"(c[3])
        : "r"(a0), "r"(a1), "r"(a2), "r"(a3), "r"(b0), "r"(b1));
}

__device__ __forceinline__ uint32_t smem_addr_u32(const void* p) {
    uint32_t a;
    asm("{ .reg .u64 t; cvta.to.shared.u64 t, %1; cvt.u32.u64 %0, t; }"
        : "=r"(a) : "l"(p));
    return a;
}
__device__ __forceinline__ void cp_async16(void* smem_dst, const void* gmem_src) {
    asm volatile("cp.async.ca.shared.global [%0], [%1], 16;"
                 :: "r"(smem_addr_u32(smem_dst)), "l"(gmem_src));
}
#define CP_COMMIT() asm volatile("cp.async.commit_group;" ::: "memory")
#define CP_WAIT2()  asm volatile("cp.async.wait_group 2;" ::: "memory")

__global__ void __launch_bounds__(512) men_gemm_kernel(
    float* __restrict__ out,
    int B)
{
    extern __shared__ uint32_t sh[];
    const int tid  = threadIdx.x;
    const int wid  = tid >> 5;
    const int lane = tid & 31;
    const int wr   = wid >> 2;          // warp row 0..3 (16 rows each)
    const int wc   = wid & 3;           // warp col 0..3 (32 cols each)
    const int gp   = lane >> 2;
    const int tg   = lane & 3;
    const int brow0 = blockIdx.x * BM;

    // stage loader: A 64x8 f4 = 512 slots (1/thread), B 128x8 = 1024 (2/thread)
    auto load_stage = [&](int k0, int st) {
        uint32_t* As = sh + st * STAGE_WORDS;
        uint32_t* Bs = As + BM * LDA;
        {
            const int r  = tid >> 3;               // 0..63
            const int kq = (tid & 7) * 4;
            cp_async16(&As[r * LDA + kq], &g_men[(brow0 + r) * K2 + k0 + kq]);
        }
#pragma unroll
        for (int q = 0; q < 2; ++q) {
            const int slot = tid * 2 + q;          // 0..1023
            const int n  = slot >> 3;              // 0..127
            const int kq = (slot & 7) * 4;
            cp_async16(&Bs[n * LDA + kq], &g_L32[n * K2 + k0 + kq]);
        }
        CP_COMMIT();
    };

    float acc[4][4];
#pragma unroll
    for (int j = 0; j < 4; ++j)
#pragma unroll
        for (int v = 0; v < 4; ++v) acc[j][v] = 0.0f;

    // prologue: 2 stages in flight
    load_stage(0 * BK, 0);
    load_stage(1 * BK, 1);

#pragma unroll
    for (int it = 0; it < NIT; ++it) {
        const int st = it % STAGES;
        if (it + 2 < NIT) load_stage((it + 2) * BK, (it + 2) % STAGES);
        else              CP_COMMIT();          // empty group keeps wait uniform
        CP_WAIT2();                             // stage `it` complete
        __syncthreads();

        const uint32_t* As = sh + st * STAGE_WORDS;
        const uint32_t* Bs = As + BM * LDA;
#pragma unroll
        for (int ks = 0; ks < BK; ks += 8) {
            const int r = wr * 16 + gp;
            const uint32_t a0 = As[r * LDA + ks + tg];
            const uint32_t a1 = As[(r + 8) * LDA + ks + tg];
            const uint32_t a2 = As[r * LDA + ks + tg + 4];
            const uint32_t a3 = As[(r + 8) * LDA + ks + tg + 4];
#pragma unroll
            for (int nt = 0; nt < 4; ++nt) {
                const int n = wc * 32 + nt * 8 + gp;
                const uint32_t b0 = Bs[n * LDA + ks + tg];
                const uint32_t b1 = Bs[n * LDA + ks + tg + 4];
                mma_tf32(acc[nt], a0, a1, a2, a3, b0, b1);
            }
        }
        __syncthreads();
    }

    // epilogue
#pragma unroll
    for (int nt = 0; nt < 4; ++nt) {
        const int row = brow0 + wr * 16 + gp;
        const int col = wc * 32 + nt * 8 + tg * 2;
        float2* o0 = reinterpret_cast<float2*>(&out[row * 128 + col]);
        float2* o1 = reinterpret_cast<float2*>(&out[(row + 8) * 128 + col]);
        *o0 = make_float2(acc[nt][0], acc[nt][1]);
        *o1 = make_float2(acc[nt][2], acc[nt][3]);
    }
}

// ---------------------------------------------------------------------------
extern "C" void kernel_launch(void* const* d_in, const int* in_sizes, int n_in,
                              void* d_out, int out_size)
{
    const int*   feat = (const int*)d_in[0];
    const int*   offs = (const int*)d_in[1];
    const float* W    = (const float*)d_in[2];
    const float* L    = (const float*)d_in[3];
    float*       out  = (float*)d_out;

    const int T = in_sizes[0];
    const int B = in_sizes[1];

    cudaFuncSetAttribute(men_gemm_kernel,
                         cudaFuncAttributeMaxDynamicSharedMemorySize,
                         GEMM_SMEM_BYTES);

    bag_reduce_kernel<<<B, 256>>>(feat, offs, W, L, T, B);
    men_gemm_kernel<<<B / BM, 512, GEMM_SMEM_BYTES>>>(out, B);
}